// round 8
// baseline (speedup 1.0000x reference)
#include <cuda_runtime.h>
#include <cstdint>
#include <cstddef>

// Problem constants (match reference)
#define KNB   32      // neighbors per node
#define D     128     // feature dim (D_IN == D_OUT == 128)
#define NPB   64      // nodes per block tile
#define NTHREADS 256  // 8 warps
#define NPW   8       // nodes per warp (NPB / 8 warps)

// SMEM layout (floats): W_s[128*128] | agg_s[NPB*128] | b_s[128]
#define SMEM_FLOATS (D*D + NPB*D + D)
#define SMEM_BYTES  (SMEM_FLOATS * 4)

__global__ __launch_bounds__(NTHREADS, 2)
void fused_softmax_agg_gemm(const float* __restrict__ neib_feats,  // [N*K, D]
                            const int*   __restrict__ neib_ids,    // [N, K]
                            const float* __restrict__ emb,         // [N_NODES+1, 1]
                            const float* __restrict__ W,           // [D, D]
                            const float* __restrict__ b,           // [D]
                            float*       __restrict__ out,         // [N, D]
                            int N)
{
    extern __shared__ float smem[];
    float* W_s   = smem;                 // 64 KB
    float* agg_s = smem + D * D;         // NPB*128 floats
    float* b_s   = agg_s + NPB * D;      // 128 floats

    const int tid  = threadIdx.x;
    const int lane = tid & 31;
    const int warp = tid >> 5;           // 0..7

    // ---- Stage W and b into shared memory once per block ----
    {
        const float4* Wg = reinterpret_cast<const float4*>(W);
        float4* Ws4 = reinterpret_cast<float4*>(W_s);
        #pragma unroll 4
        for (int i = tid; i < (D * D) / 4; i += NTHREADS) Ws4[i] = Wg[i];
        if (tid < D) b_s[tid] = b[tid];
    }

    const int numTiles = (N + NPB - 1) / NPB;

    for (int tile = blockIdx.x; tile < numTiles; tile += gridDim.x) {
        const int base  = tile * NPB;
        const int node0 = base + warp * NPW;   // this warp's first node

        // Barrier: (a) first iter: W_s/b_s staged before GEMM,
        // (b) later iters: previous GEMM done reading agg_s before overwrite.
        __syncthreads();

        // ---- Phase 1a: compute ALL softmax weights for this warp's 8 nodes ----
        // 8 independent gather chains + 8 independent shuffle-reductions:
        // latency overlaps across nodes instead of serializing per node.
        float wgt[NPW];
        {
            int   ids[NPW];
            float e[NPW];
            #pragma unroll
            for (int nt = 0; nt < NPW; ++nt) {
                const int node = node0 + nt;
                ids[nt] = (node < N) ? __ldg(&neib_ids[node * KNB + lane]) : 0;
            }
            #pragma unroll
            for (int nt = 0; nt < NPW; ++nt)
                e[nt] = __ldg(&emb[ids[nt]]);
            #pragma unroll
            for (int nt = 0; nt < NPW; ++nt) {
                float m = e[nt];
                #pragma unroll
                for (int o = 16; o; o >>= 1)
                    m = fmaxf(m, __shfl_xor_sync(0xffffffffu, m, o));
                const float p = expf(e[nt] - m);
                float s = p;
                #pragma unroll
                for (int o = 16; o; o >>= 1)
                    s += __shfl_xor_sync(0xffffffffu, s, o);
                wgt[nt] = p / s;
            }
        }

        // ---- Phase 1b: pure streaming aggregation (weights already in regs) ----
        // Only inter-node gap is the FMA drain; loads of node nt+1 are
        // independent of node nt, so ptxas keeps the LSU queue full.
        #pragma unroll
        for (int nt = 0; nt < NPW; ++nt) {
            const int node = node0 + nt;
            float4* arow = reinterpret_cast<float4*>(agg_s + (warp * NPW + nt) * D);
            if (node < N) {
                const float4* frow =
                    reinterpret_cast<const float4*>(neib_feats + (size_t)node * (KNB * D));
                float4 acc = make_float4(0.f, 0.f, 0.f, 0.f);
                #pragma unroll
                for (int k = 0; k < KNB; ++k) {
                    const float wk = __shfl_sync(0xffffffffu, wgt[nt], k);
                    const float4 f = __ldcs(&frow[k * (D / 4) + lane]);
                    acc.x = fmaf(wk, f.x, acc.x);
                    acc.y = fmaf(wk, f.y, acc.y);
                    acc.z = fmaf(wk, f.z, acc.z);
                    acc.w = fmaf(wk, f.w, acc.w);
                }
                arow[lane] = acc;
            } else {
                arow[lane] = make_float4(0.f, 0.f, 0.f, 0.f);
            }
        }

        __syncthreads();

        // ---- Phase 2: tile GEMM  out[64,128] = agg[64,128] @ W[128,128] + b ----
        // Thread (warp, lane): nodes [warp*8, warp*8+8), cols [4*lane, 4*lane+4).
        const float4 bv = reinterpret_cast<const float4*>(b_s)[lane];
        float4 C[8];
        #pragma unroll
        for (int m = 0; m < 8; ++m) C[m] = bv;

        const float* ap = agg_s + warp * NPW * D;

        #pragma unroll 8
        for (int i4 = 0; i4 < D / 4; ++i4) {
            float4 av[8];
            #pragma unroll
            for (int m = 0; m < 8; ++m)
                av[m] = *reinterpret_cast<const float4*>(ap + m * D + i4 * 4);
            #pragma unroll
            for (int j = 0; j < 4; ++j) {
                const float4 wv =
                    *reinterpret_cast<const float4*>(W_s + (i4 * 4 + j) * D + 4 * lane);
                #pragma unroll
                for (int m = 0; m < 8; ++m) {
                    const float a = (&av[m].x)[j];
                    C[m].x = fmaf(a, wv.x, C[m].x);
                    C[m].y = fmaf(a, wv.y, C[m].y);
                    C[m].z = fmaf(a, wv.z, C[m].z);
                    C[m].w = fmaf(a, wv.w, C[m].w);
                }
            }
        }

        #pragma unroll
        for (int m = 0; m < 8; ++m) {
            const int node = base + warp * NPW + m;
            if (node < N)
                __stcs(&reinterpret_cast<float4*>(out + (size_t)node * D)[lane], C[m]);
        }
    }
}

extern "C" void kernel_launch(void* const* d_in, const int* in_sizes, int n_in,
                              void* d_out, int out_size)
{
    // metadata order: node_feats, neib_feats, node_ids, neib_ids, emb, W, b
    const float* neib_feats = (const float*)d_in[1];
    const int*   neib_ids   = (const int*)  d_in[3];
    const float* emb        = (const float*)d_in[4];
    const float* W          = (const float*)d_in[5];
    const float* b          = (const float*)d_in[6];
    float*       out        = (float*)d_out;

    const int N = in_sizes[3] / KNB;   // neib_ids has N*K elements

    // Opt in to >48KB dynamic SMEM (idempotent; not a stream-ordered call).
    cudaFuncSetAttribute(fused_softmax_agg_gemm,
                         cudaFuncAttributeMaxDynamicSharedMemorySize, SMEM_BYTES);

    const int numTiles = (N + NPB - 1) / NPB;
    int grid = 2 * 152;                 // 2 blocks/SM on GB300 (152 SMs)
    if (grid > numTiles) grid = numTiles;

    fused_softmax_agg_gemm<<<grid, NTHREADS, SMEM_BYTES>>>(
        neib_feats, neib_ids, emb, W, b, out, N);
}

// round 17
// speedup vs baseline: 1.0375x; 1.0375x over previous
#include <cuda_runtime.h>
#include <cstdint>
#include <cstddef>

// Problem constants (match reference)
#define KNB   32      // neighbors per node
#define D     128     // feature dim (D_IN == D_OUT == 128)
#define NTHREADS 256  // 8 warps
#define NPW   8       // nodes per warp-tile
#define WPB   (NTHREADS / 32)

// SMEM layout (floats): W_s[128*128] | agg_s[WPB*NPW*128] | b_s[128]
#define SMEM_FLOATS (D*D + WPB*NPW*D + D)
#define SMEM_BYTES  (SMEM_FLOATS * 4)

__global__ __launch_bounds__(NTHREADS, 2)
void fused_softmax_agg_gemm(const float* __restrict__ neib_feats,  // [N*K, D]
                            const int*   __restrict__ neib_ids,    // [N, K]
                            const float* __restrict__ emb,         // [N_NODES+1, 1]
                            const float* __restrict__ W,           // [D, D]
                            const float* __restrict__ b,           // [D]
                            float*       __restrict__ out,         // [N, D]
                            int N)
{
    extern __shared__ float smem[];
    float* W_s   = smem;                       // 64 KB, read-only after stage
    float* agg_s = smem + D * D;               // per-warp private 8x128 regions
    float* b_s   = agg_s + WPB * NPW * D;      // 128 floats

    const int tid  = threadIdx.x;
    const int lane = tid & 31;
    const int warp = tid >> 5;                 // 0..7

    // ---- Stage W and b into shared memory once per block ----
    {
        const float4* Wg = reinterpret_cast<const float4*>(W);
        float4* Ws4 = reinterpret_cast<float4*>(W_s);
        #pragma unroll 4
        for (int i = tid; i < (D * D) / 4; i += NTHREADS) Ws4[i] = Wg[i];
        if (tid < D) b_s[tid] = b[tid];
    }
    // ONLY block-wide barrier in the kernel: W_s/b_s visible to all warps.
    __syncthreads();

    // Each warp is an INDEPENDENT pipeline over 8-node tiles. No further
    // block barriers -> warps drift out of phase, so at any instant some
    // warps stream neib_feats (keeping DRAM busy) while others run their
    // SMEM GEMM (consuming otherwise-idle FFMA issue slots).
    float* aggw = agg_s + warp * NPW * D;      // this warp's private staging
    const float4 bv = reinterpret_cast<const float4*>(b_s)[lane];

    const int numWarpTiles = (N + NPW - 1) / NPW;
    const int gwarp   = blockIdx.x * WPB + warp;
    const int gstride = gridDim.x * WPB;

    for (int wt = gwarp; wt < numWarpTiles; wt += gstride) {
        const int node0 = wt * NPW;

        // ---- Phase 1a: softmax weights for all 8 nodes (indep. chains) ----
        float wgt[NPW];
        {
            int   ids[NPW];
            float e[NPW];
            #pragma unroll
            for (int nt = 0; nt < NPW; ++nt) {
                const int node = node0 + nt;
                ids[nt] = (node < N) ? __ldg(&neib_ids[node * KNB + lane]) : 0;
            }
            #pragma unroll
            for (int nt = 0; nt < NPW; ++nt)
                e[nt] = __ldg(&emb[ids[nt]]);
            #pragma unroll
            for (int nt = 0; nt < NPW; ++nt) {
                float m = e[nt];
                #pragma unroll
                for (int o = 16; o; o >>= 1)
                    m = fmaxf(m, __shfl_xor_sync(0xffffffffu, m, o));
                const float p = expf(e[nt] - m);
                float s = p;
                #pragma unroll
                for (int o = 16; o; o >>= 1)
                    s += __shfl_xor_sync(0xffffffffu, s, o);
                wgt[nt] = p / s;
            }
        }

        // ---- Phase 1b: streaming weighted aggregation into private SMEM ----
        #pragma unroll
        for (int nt = 0; nt < NPW; ++nt) {
            const int node = node0 + nt;
            float4* arow = reinterpret_cast<float4*>(aggw + nt * D);
            if (node < N) {
                const float4* frow =
                    reinterpret_cast<const float4*>(neib_feats + (size_t)node * (KNB * D));
                float4 acc = make_float4(0.f, 0.f, 0.f, 0.f);
                #pragma unroll
                for (int k = 0; k < KNB; ++k) {
                    const float wk = __shfl_sync(0xffffffffu, wgt[nt], k);
                    const float4 f = __ldcs(&frow[k * (D / 4) + lane]);
                    acc.x = fmaf(wk, f.x, acc.x);
                    acc.y = fmaf(wk, f.y, acc.y);
                    acc.z = fmaf(wk, f.z, acc.z);
                    acc.w = fmaf(wk, f.w, acc.w);
                }
                arow[lane] = acc;
            } else {
                arow[lane] = make_float4(0.f, 0.f, 0.f, 0.f);
            }
        }

        // Warp-local visibility of agg rows (cross-lane reads below).
        __syncwarp();

        // ---- Phase 2: per-warp GEMM  out[8,128] = agg[8,128] @ W + b ----
        float4 C[NPW];
        #pragma unroll
        for (int m = 0; m < NPW; ++m) C[m] = bv;

        #pragma unroll 8
        for (int i4 = 0; i4 < D / 4; ++i4) {
            float4 av[NPW];
            #pragma unroll
            for (int m = 0; m < NPW; ++m)
                av[m] = *reinterpret_cast<const float4*>(aggw + m * D + i4 * 4);
            #pragma unroll
            for (int j = 0; j < 4; ++j) {
                const float4 wv =
                    *reinterpret_cast<const float4*>(W_s + (i4 * 4 + j) * D + 4 * lane);
                #pragma unroll
                for (int m = 0; m < NPW; ++m) {
                    const float a = (&av[m].x)[j];
                    C[m].x = fmaf(a, wv.x, C[m].x);
                    C[m].y = fmaf(a, wv.y, C[m].y);
                    C[m].z = fmaf(a, wv.z, C[m].z);
                    C[m].w = fmaf(a, wv.w, C[m].w);
                }
            }
        }

        #pragma unroll
        for (int m = 0; m < NPW; ++m) {
            const int node = node0 + m;
            if (node < N)
                __stcs(&reinterpret_cast<float4*>(out + (size_t)node * D)[lane], C[m]);
        }

        // Ensure all lanes finished reading aggw before next tile overwrites.
        __syncwarp();
    }
}

extern "C" void kernel_launch(void* const* d_in, const int* in_sizes, int n_in,
                              void* d_out, int out_size)
{
    // metadata order: node_feats, neib_feats, node_ids, neib_ids, emb, W, b
    const float* neib_feats = (const float*)d_in[1];
    const int*   neib_ids   = (const int*)  d_in[3];
    const float* emb        = (const float*)d_in[4];
    const float* W          = (const float*)d_in[5];
    const float* b          = (const float*)d_in[6];
    float*       out        = (float*)d_out;

    const int N = in_sizes[3] / KNB;   // neib_ids has N*K elements

    // Opt in to >48KB dynamic SMEM (idempotent; not a stream-ordered call).
    cudaFuncSetAttribute(fused_softmax_agg_gemm,
                         cudaFuncAttributeMaxDynamicSharedMemorySize, SMEM_BYTES);

    const int numWarpTiles = (N + NPW - 1) / NPW;
    int grid = 2 * 152;                 // 2 blocks/SM on GB300 (152 SMs)
    const int maxGrid = (numWarpTiles + WPB - 1) / WPB;
    if (grid > maxGrid) grid = maxGrid;

    fused_softmax_agg_gemm<<<grid, NTHREADS, SMEM_BYTES>>>(
        neib_feats, neib_ids, emb, W, b, out, N);
}